// round 12
// baseline (speedup 1.0000x reference)
#include <cuda_runtime.h>
#include <cuda_fp16.h>
#include <cstdint>

#define BB 4
#define LL 1024
#define VV 50257
#define DD 512

// ---- scratch (no allocations allowed) ----
__device__ float  g_xproj[BB * LL * DD];          // [b*L+t][D] fp32
__device__ __half g_hs_h[BB * LL * DD];           // [b*L+t][D] fp16 (K3 A operand)
__device__ __half g_wo_h[(size_t)VV * DD];        // Wo as fp16

// =====================================================================
// helpers (base sm_103 ISA only — no 'a'-suffix features)
// =====================================================================
__device__ __forceinline__ uint32_t smem_u32(const void* p)
{
    uint32_t a;
    asm("{ .reg .u64 t; cvta.to.shared.u64 t, %1; cvt.u32.u64 %0, t; }" : "=r"(a) : "l"(p));
    return a;
}
#define SWZ128(x) ((x) ^ (((x) >> 3) & 0x70))

__device__ __forceinline__ void cpa16(uint32_t dst, const void* src, bool valid)
{
    asm volatile("cp.async.cg.shared.global [%0], [%1], 16, %2;"
                 :: "r"(dst), "l"(src), "r"(valid ? 16 : 0));
}
__device__ __forceinline__ void cpa_commit() { asm volatile("cp.async.commit_group;"); }
template <int N> __device__ __forceinline__ void cpa_wait() { asm volatile("cp.async.wait_group %0;" :: "n"(N)); }

__device__ __forceinline__ void ldm4(uint32_t* r, uint32_t addr)
{
    asm volatile("ldmatrix.sync.aligned.m8n8.x4.shared.b16 {%0,%1,%2,%3}, [%4];"
                 : "=r"(r[0]), "=r"(r[1]), "=r"(r[2]), "=r"(r[3]) : "r"(addr));
}
__device__ __forceinline__ void mma16816(float* c, const uint32_t* a, uint32_t b0, uint32_t b1)
{
    asm volatile("mma.sync.aligned.m16n8k16.row.col.f32.f16.f16.f32 "
                 "{%0,%1,%2,%3}, {%4,%5,%6,%7}, {%8,%9}, {%0,%1,%2,%3};"
                 : "+f"(c[0]), "+f"(c[1]), "+f"(c[2]), "+f"(c[3])
                 : "r"(a[0]), "r"(a[1]), "r"(a[2]), "r"(a[3]), "r"(b0), "r"(b1));
}
__device__ __forceinline__ void st_cluster_f32(uint32_t laddr, uint32_t rank, float v)
{
    uint32_t ra;
    asm volatile("mapa.shared::cluster.u32 %0, %1, %2;" : "=r"(ra) : "r"(laddr), "r"(rank));
    asm volatile("st.shared::cluster.f32 [%0], %1;" :: "r"(ra), "f"(v) : "memory");
}
#define CL_ARRIVE() asm volatile("barrier.cluster.arrive.aligned;" ::: "memory")
#define CL_WAIT()   asm volatile("barrier.cluster.wait.aligned;" ::: "memory")

// packed f32x2 (base sm_103 ISA)
__device__ __forceinline__ unsigned long long pk2(float lo, float hi)
{
    unsigned long long r;
    asm("mov.b64 %0, {%1, %2};" : "=l"(r) : "f"(lo), "f"(hi));
    return r;
}
__device__ __forceinline__ void fma2(unsigned long long& d, unsigned long long a, unsigned long long b)
{
    asm("fma.rn.f32x2 %0, %1, %2, %0;" : "+l"(d) : "l"(a), "l"(b));
}
__device__ __forceinline__ float2 upk2(unsigned long long v)
{
    float2 r;
    asm("mov.b64 {%0, %1}, %2;" : "=f"(r.x), "=f"(r.y) : "l"(v));
    return r;
}

// =====================================================================
// K0: Wo fp32 -> fp16 (separate launch — de-risked from round 10)
// =====================================================================
__global__ void k0_conv(const float* __restrict__ Wo)
{
    const size_t i4 = (size_t)blockIdx.x * blockDim.x + threadIdx.x;
    if (i4 * 4 >= (size_t)VV * DD) return;
    float4 v = *(const float4*)(Wo + i4 * 4);
    __half2* dst = (__half2*)(g_wo_h + i4 * 4);
    dst[0] = __floats2half2_rn(v.x, v.y);
    dst[1] = __floats2half2_rn(v.z, v.w);
}

// =====================================================================
// K1: xproj = emb[tok] @ Wx^T + bx   (M=4096, N=512, K=512)
// =====================================================================
__global__ void k1_xproj(const int* __restrict__ tok, const float* __restrict__ emb,
                         const float* __restrict__ Wx, const float* __restrict__ bx)
{
    __shared__ float As[16][64];
    __shared__ float Bs[16][64];
    __shared__ int toks[64];
    const int m0 = blockIdx.y * 64;
    const int n0 = blockIdx.x * 64;
    const int tid = threadIdx.x;
    if (tid < 64) toks[tid] = tok[m0 + tid];
    __syncthreads();
    const int tm = tid >> 4, tn = tid & 15;
    const int lr = tid >> 2;
    const int lk = (tid & 3) << 2;
    const float* arow = emb + (size_t)toks[lr] * DD + lk;
    const float* brow = Wx + (size_t)(n0 + lr) * DD + lk;
    float acc[4][4] = {};
    for (int k0 = 0; k0 < DD; k0 += 16) {
        float4 av = *(const float4*)(arow + k0);
        float4 bv = *(const float4*)(brow + k0);
        __syncthreads();
        As[lk + 0][lr] = av.x; As[lk + 1][lr] = av.y;
        As[lk + 2][lr] = av.z; As[lk + 3][lr] = av.w;
        Bs[lk + 0][lr] = bv.x; Bs[lk + 1][lr] = bv.y;
        Bs[lk + 2][lr] = bv.z; Bs[lk + 3][lr] = bv.w;
        __syncthreads();
        #pragma unroll
        for (int k = 0; k < 16; k++) {
            float a[4], b[4];
            *(float4*)a = *(const float4*)&As[k][tm * 4];
            *(float4*)b = *(const float4*)&Bs[k][tn * 4];
            #pragma unroll
            for (int i = 0; i < 4; i++)
                #pragma unroll
                for (int j = 0; j < 4; j++)
                    acc[i][j] = fmaf(a[i], b[j], acc[i][j]);
        }
    }
    #pragma unroll
    for (int i = 0; i < 4; i++) {
        const int m = m0 + tm * 4 + i;
        #pragma unroll
        for (int j = 0; j < 4; j++) {
            const int e = n0 + tn * 4 + j;
            g_xproj[(size_t)m * DD + e] = acc[i][j] + bx[e];
        }
    }
}

// =====================================================================
// K2: recurrence, TWO batches per 8-CTA cluster under ONE cluster
// barrier per step (grid = 16 CTAs = 2 clusters). Batch A's DSMEM
// store-drain hides behind batch B's compute; one wait serves both.
// Per-lane layout: d = 4*lane + 128*q -> LDS.128 + packed f32x2 dots.
// Parity safety: wait#t pairs with arrive#(t-1); peers' reads of
// buffer (t&1) at step t-1 completed before their arrive#(t-1), so
// step-t writes to (t&1) cannot overtake them.
// =====================================================================
__global__ __launch_bounds__(512, 1) __cluster_dims__(8, 1, 1)
void k2_recur(const float* __restrict__ Wh, const float* __restrict__ bh)
{
    __shared__ float shA[2][DD];
    __shared__ float shB[2][DD];
    const int tid = threadIdx.x;
    const int lane = tid & 31;
    const int w = tid >> 5;                 // 0..15
    const int cl = blockIdx.x >> 3;         // 0..1 (batch pair)
    const int crank = blockIdx.x & 7;
    const int e_base = crank * 64 + w * 4;  // this warp's 4 e's

    // packed weights (shared by both batches)
    unsigned long long wp[4][8];
    float bias[4];
    #pragma unroll
    for (int j = 0; j < 4; j++) {
        bias[j] = bh[e_base + j];
        #pragma unroll
        for (int q = 0; q < 4; q++) {
            float4 wv = *(const float4*)(Wh + (size_t)(e_base + j) * DD + 4 * lane + 128 * q);
            wp[j][2 * q]     = pk2(wv.x, wv.y);
            wp[j][2 * q + 1] = pk2(wv.z, wv.w);
        }
    }
    const float* xpA = g_xproj + (size_t)(2 * cl) * LL * DD;
    const float* xpB = g_xproj + (size_t)(2 * cl + 1) * LL * DD;
    __half* hsA = g_hs_h + (size_t)(2 * cl) * LL * DD;
    __half* hsB = g_hs_h + (size_t)(2 * cl + 1) * LL * DD;

    // ---- t = 0 (h_prev = 0) ----
    {
        float vA[4], vB[4];
        #pragma unroll
        for (int j = 0; j < 4; j++) {
            vA[j] = fmaxf(bias[j] + __ldcg(xpA + e_base + j), 0.f);
            vB[j] = fmaxf(bias[j] + __ldcg(xpB + e_base + j), 0.f);
        }
        if (lane < 8) {
            #pragma unroll
            for (int j = 0; j < 4; j++) {
                st_cluster_f32(smem_u32(&shA[0][e_base + j]), lane, vA[j]);
                st_cluster_f32(smem_u32(&shB[0][e_base + j]), lane, vB[j]);
            }
        }
        CL_ARRIVE();
        if (lane == 8) {
            __half2* dA = (__half2*)(hsA + e_base);
            dA[0] = __floats2half2_rn(vA[0], vA[1]);
            dA[1] = __floats2half2_rn(vA[2], vA[3]);
            __half2* dB = (__half2*)(hsB + e_base);
            dB[0] = __floats2half2_rn(vB[0], vB[1]);
            dB[1] = __floats2half2_rn(vB[2], vB[3]);
        }
    }

    // prefetch xv for t = 1
    float xvA_n[4], xvB_n[4];
    #pragma unroll
    for (int j = 0; j < 4; j++) {
        xvA_n[j] = __ldcg(xpA + (size_t)DD + e_base + j);
        xvB_n[j] = __ldcg(xpB + (size_t)DD + e_base + j);
    }

    for (int t = 1; t < LL; t++) {
        const int rb = (t - 1) & 1;
        const int wb = t & 1;
        const bool more = (t < LL - 1);
        CL_WAIT();                      // both batches' h_{t-1} visible

        // ================= batch A =================
        float vA[4];
        {
            const float* hb = shA[rb];
            unsigned long long hp[8];
            #pragma unroll
            for (int q = 0; q < 4; q++) {
                float4 hv = *(const float4*)(hb + 4 * lane + 128 * q);
                hp[2 * q]     = pk2(hv.x, hv.y);
                hp[2 * q + 1] = pk2(hv.z, hv.w);
            }
            float xv[4];
            #pragma unroll
            for (int j = 0; j < 4; j++) xv[j] = xvA_n[j];
            if (more) {
                #pragma unroll
                for (int j = 0; j < 4; j++)
                    xvA_n[j] = __ldcg(xpA + (size_t)(t + 1) * DD + e_base + j);
            }
            float acc[4];
            #pragma unroll
            for (int j = 0; j < 4; j++) {
                unsigned long long a2 = 0ull;
                #pragma unroll
                for (int q = 0; q < 8; q++) fma2(a2, wp[j][q], hp[q]);
                float2 h2 = upk2(a2);
                acc[j] = h2.x + h2.y;
            }
            #pragma unroll
            for (int off = 16; off > 0; off >>= 1)
                #pragma unroll
                for (int j = 0; j < 4; j++)
                    acc[j] += __shfl_xor_sync(0xffffffffu, acc[j], off);
            #pragma unroll
            for (int j = 0; j < 4; j++)
                vA[j] = fmaxf(acc[j] + bias[j] + xv[j], 0.f);
            if (more && lane < 8) {
                #pragma unroll
                for (int j = 0; j < 4; j++)
                    st_cluster_f32(smem_u32(&shA[wb][e_base + j]), lane, vA[j]);
            }
        }

        // ================= batch B =================
        float vB[4];
        {
            const float* hb = shB[rb];
            unsigned long long hp[8];
            #pragma unroll
            for (int q = 0; q < 4; q++) {
                float4 hv = *(const float4*)(hb + 4 * lane + 128 * q);
                hp[2 * q]     = pk2(hv.x, hv.y);
                hp[2 * q + 1] = pk2(hv.z, hv.w);
            }
            float xv[4];
            #pragma unroll
            for (int j = 0; j < 4; j++) xv[j] = xvB_n[j];
            if (more) {
                #pragma unroll
                for (int j = 0; j < 4; j++)
                    xvB_n[j] = __ldcg(xpB + (size_t)(t + 1) * DD + e_base + j);
            }
            float acc[4];
            #pragma unroll
            for (int j = 0; j < 4; j++) {
                unsigned long long a2 = 0ull;
                #pragma unroll
                for (int q = 0; q < 8; q++) fma2(a2, wp[j][q], hp[q]);
                float2 h2 = upk2(a2);
                acc[j] = h2.x + h2.y;
            }
            #pragma unroll
            for (int off = 16; off > 0; off >>= 1)
                #pragma unroll
                for (int j = 0; j < 4; j++)
                    acc[j] += __shfl_xor_sync(0xffffffffu, acc[j], off);
            #pragma unroll
            for (int j = 0; j < 4; j++)
                vB[j] = fmaxf(acc[j] + bias[j] + xv[j], 0.f);
            if (more && lane < 8) {
                #pragma unroll
                for (int j = 0; j < 4; j++)
                    st_cluster_f32(smem_u32(&shB[wb][e_base + j]), lane, vB[j]);
            }
        }

        if (more) CL_ARRIVE();

        // hs stores AFTER arrive (off the release critical path)
        if (lane == 8) {
            __half2* dA = (__half2*)(hsA + (size_t)t * DD + e_base);
            dA[0] = __floats2half2_rn(vA[0], vA[1]);
            dA[1] = __floats2half2_rn(vA[2], vA[3]);
            __half2* dB = (__half2*)(hsB + (size_t)t * DD + e_base);
            dB[0] = __floats2half2_rn(vB[0], vB[1]);
            dB[1] = __floats2half2_rn(vB[2], vB[3]);
        }
    }
}

// =====================================================================
// K3: out = hs @ Wo^T + bo  (M=4096, N=50257, K=512) — fp16 HMMA.
// CTA 128x128, warp tile 64x32 (2m x 4n), BK=64, 3-stage cp.async,
// 2 CTAs/SM, single sync per chunk (no trailing sync: issue(c+2)
// targets stage (c-1)%3 whose reads finished before the top sync).
// bo tile in smem. VV odd => scalar fp32 stores. (measured 681us)
// =====================================================================
#define K3_BM 128
#define K3_BN 128
#define K3_BKH 64
#define K3_NCH (DD / K3_BKH)                     // 8
#define K3_STAGE_BYTES ((K3_BM + K3_BN) * 128)   // 32768
#define K3_STAGES 3
#define K3_SMEM_BYTES (K3_STAGES * K3_STAGE_BYTES + K3_BN * 4)  // 98816

__global__ __launch_bounds__(256, 2)
void k3_mma(const float* __restrict__ bo, float* __restrict__ out)
{
    extern __shared__ __align__(1024) char smc[];
    const uint32_t smem_base = smem_u32(smc);
    float* bo_s = (float*)(smc + K3_STAGES * K3_STAGE_BYTES);
    const int tid = threadIdx.x;
    const int wid = tid >> 5;
    const int lane = tid & 31;
    const int m0 = blockIdx.x * K3_BM;
    const int n0 = blockIdx.y * K3_BN;
    const int warp_m = (wid & 1) * 64;
    const int warp_n = (wid >> 1) * 32;

    if (tid < K3_BN) {
        const int v = n0 + tid;
        bo_s[tid] = (v < VV) ? bo[v] : 0.f;
    }

    // ---- loader: 16B segs, swizzled 128B rows
    const int seg = tid & 7;
    const int r0 = tid >> 3;      // 0..31
    auto issue = [&](int c, int s) {
        const uint32_t abase = smem_base + s * K3_STAGE_BYTES;
        const uint32_t bbase = abase + K3_BM * 128;
        const __half* asrc = g_hs_h + (size_t)(m0 + r0) * DD + c * K3_BKH + seg * 8;
        #pragma unroll
        for (int i = 0; i < 4; i++) {
            const int row = r0 + 32 * i;
            cpa16(abase + SWZ128(row * 128 + seg * 16), asrc + (size_t)32 * i * DD, true);
        }
        #pragma unroll
        for (int i = 0; i < 4; i++) {
            const int row = r0 + 32 * i;
            const int v = n0 + row;
            const __half* bsrc = g_wo_h + (size_t)(v < VV ? v : 0) * DD + c * K3_BKH + seg * 8;
            cpa16(bbase + SWZ128(row * 128 + seg * 16), bsrc, v < VV);
        }
        cpa_commit();
    };

    issue(0, 0);
    issue(1, 1);

    // ldmatrix lane geometry
    int arow[4], axor[4];
    #pragma unroll
    for (int f = 0; f < 4; f++) {
        const int row = warp_m + f * 16 + (lane & 15);
        arow[f] = row * 128;
        axor[f] = (row & 7) * 16;
    }
    const int acol0 = (lane >> 4) * 16;
    int brow[2], bxor[2];
    #pragma unroll
    for (int g = 0; g < 2; g++) {
        const int nr = warp_n + g * 16 + ((lane & 16) >> 1) + (lane & 7);
        brow[g] = nr * 128;
        bxor[g] = (nr & 7) * 16;
    }
    const int bcol0 = ((lane >> 3) & 1) * 16;

    float acc[4][4][4];
    #pragma unroll
    for (int i = 0; i < 4; i++)
        #pragma unroll
        for (int j = 0; j < 4; j++)
            #pragma unroll
            for (int q = 0; q < 4; q++) acc[i][j][q] = 0.f;

    for (int c = 0; c < K3_NCH; c++) {
        if (c == K3_NCH - 1) cpa_wait<0>(); else cpa_wait<1>();
        __syncthreads();
        if (c + 2 < K3_NCH) issue(c + 2, (c + 2) % K3_STAGES);

        const uint32_t Ast = smem_base + (c % K3_STAGES) * K3_STAGE_BYTES;
        const uint32_t Bst = Ast + K3_BM * 128;

        #pragma unroll
        for (int ks = 0; ks < 4; ks++) {
            uint32_t A[4][4];
            #pragma unroll
            for (int f = 0; f < 4; f++)
                ldm4(A[f], Ast + arow[f] + ((acol0 + 32 * ks) ^ axor[f]));
            uint32_t Bf[2][4];
            #pragma unroll
            for (int g = 0; g < 2; g++)
                ldm4(Bf[g], Bst + brow[g] + ((bcol0 + 32 * ks) ^ bxor[g]));
            #pragma unroll
            for (int fm = 0; fm < 4; fm++)
                #pragma unroll
                for (int g = 0; g < 2; g++) {
                    mma16816(acc[fm][2 * g],     A[fm], Bf[g][0], Bf[g][1]);
                    mma16816(acc[fm][2 * g + 1], A[fm], Bf[g][2], Bf[g][3]);
                }
        }
        // no trailing sync (see header comment)
    }

    // ---- epilogue: scalar 32-bit stores (VV odd => rows only 4B-aligned)
    #pragma unroll
    for (int fm = 0; fm < 4; fm++) {
        const int m = m0 + warp_m + fm * 16 + (lane >> 2);
        float* orow0 = out + (size_t)m * VV;
        float* orow1 = out + (size_t)(m + 8) * VV;
        #pragma unroll
        for (int fn = 0; fn < 4; fn++) {
            const int nloc = warp_n + fn * 8 + 2 * (lane & 3);
            const int v = n0 + nloc;
            if (v < VV) {
                const float b0 = bo_s[nloc];
                orow0[v] = acc[fm][fn][0] + b0;
                orow1[v] = acc[fm][fn][2] + b0;
            }
            if (v + 1 < VV) {
                const float b1 = bo_s[nloc + 1];
                orow0[v + 1] = acc[fm][fn][1] + b1;
                orow1[v + 1] = acc[fm][fn][3] + b1;
            }
        }
    }
}

// =====================================================================
extern "C" void kernel_launch(void* const* d_in, const int* in_sizes, int n_in,
                              void* d_out, int out_size)
{
    const int*   tok = (const int*)d_in[0];
    const float* emb = (const float*)d_in[1];
    const float* Wh  = (const float*)d_in[2];
    const float* bh  = (const float*)d_in[3];
    const float* Wx  = (const float*)d_in[4];
    const float* bx  = (const float*)d_in[5];
    const float* Wo  = (const float*)d_in[6];
    const float* bo  = (const float*)d_in[7];
    float* out = (float*)d_out;

    const size_t n4 = ((size_t)VV * DD) / 4;
    k0_conv<<<(unsigned)((n4 + 255) / 256), 256>>>(Wo);

    dim3 g1(DD / 64, (BB * LL) / 64);
    k1_xproj<<<g1, 256>>>(tok, emb, Wx, bx);

    k2_recur<<<16, 512>>>(Wh, bh);   // 2 clusters x 8 CTAs, 2 batches each

    cudaFuncSetAttribute(k3_mma, cudaFuncAttributeMaxDynamicSharedMemorySize, K3_SMEM_BYTES);
    dim3 g3((BB * LL) / K3_BM, (VV + K3_BN - 1) / K3_BN);   // (32, 393), M fastest
    k3_mma<<<g3, 256, K3_SMEM_BYTES>>>(bo, out);
}

// round 13
// speedup vs baseline: 1.5331x; 1.5331x over previous
#include <cuda_runtime.h>
#include <cuda_fp16.h>
#include <cstdint>

#define BB 4
#define LL 1024
#define VV 50257
#define DD 512

// ---- scratch (no allocations allowed) ----
__device__ float  g_xproj[BB * LL * DD];          // [b*L+t][D] fp32
__device__ __half g_hs_h[BB * LL * DD];           // [b*L+t][D] fp16 (K3 A operand)
__device__ __half g_wo_h[(size_t)VV * DD];        // Wo as fp16

// =====================================================================
// helpers (base sm_103 ISA only — no 'a'-suffix features)
// =====================================================================
__device__ __forceinline__ uint32_t smem_u32(const void* p)
{
    uint32_t a;
    asm("{ .reg .u64 t; cvta.to.shared.u64 t, %1; cvt.u32.u64 %0, t; }" : "=r"(a) : "l"(p));
    return a;
}
#define SWZ128(x) ((x) ^ (((x) >> 3) & 0x70))

__device__ __forceinline__ void cpa16(uint32_t dst, const void* src, bool valid)
{
    asm volatile("cp.async.cg.shared.global [%0], [%1], 16, %2;"
                 :: "r"(dst), "l"(src), "r"(valid ? 16 : 0));
}
__device__ __forceinline__ void cpa_commit() { asm volatile("cp.async.commit_group;"); }
template <int N> __device__ __forceinline__ void cpa_wait() { asm volatile("cp.async.wait_group %0;" :: "n"(N)); }

__device__ __forceinline__ void ldm4(uint32_t* r, uint32_t addr)
{
    asm volatile("ldmatrix.sync.aligned.m8n8.x4.shared.b16 {%0,%1,%2,%3}, [%4];"
                 : "=r"(r[0]), "=r"(r[1]), "=r"(r[2]), "=r"(r[3]) : "r"(addr));
}
__device__ __forceinline__ void mma16816(float* c, const uint32_t* a, uint32_t b0, uint32_t b1)
{
    asm volatile("mma.sync.aligned.m16n8k16.row.col.f32.f16.f16.f32 "
                 "{%0,%1,%2,%3}, {%4,%5,%6,%7}, {%8,%9}, {%0,%1,%2,%3};"
                 : "+f"(c[0]), "+f"(c[1]), "+f"(c[2]), "+f"(c[3])
                 : "r"(a[0]), "r"(a[1]), "r"(a[2]), "r"(a[3]), "r"(b0), "r"(b1));
}
__device__ __forceinline__ void st_cluster_f32(uint32_t laddr, uint32_t rank, float v)
{
    uint32_t ra;
    asm volatile("mapa.shared::cluster.u32 %0, %1, %2;" : "=r"(ra) : "r"(laddr), "r"(rank));
    asm volatile("st.shared::cluster.f32 [%0], %1;" :: "r"(ra), "f"(v) : "memory");
}
#define CL_ARRIVE() asm volatile("barrier.cluster.arrive.aligned;" ::: "memory")
#define CL_WAIT()   asm volatile("barrier.cluster.wait.aligned;" ::: "memory")

// packed f32x2 (base sm_103 ISA)
__device__ __forceinline__ unsigned long long pk2(float lo, float hi)
{
    unsigned long long r;
    asm("mov.b64 %0, {%1, %2};" : "=l"(r) : "f"(lo), "f"(hi));
    return r;
}
__device__ __forceinline__ void fma2(unsigned long long& d, unsigned long long a, unsigned long long b)
{
    asm("fma.rn.f32x2 %0, %1, %2, %0;" : "+l"(d) : "l"(a), "l"(b));
}
__device__ __forceinline__ float2 upk2(unsigned long long v)
{
    float2 r;
    asm("mov.b64 {%0, %1}, %2;" : "=f"(r.x), "=f"(r.y) : "l"(v));
    return r;
}

// =====================================================================
// K0: Wo fp32 -> fp16
// =====================================================================
__global__ void k0_conv(const float* __restrict__ Wo)
{
    const size_t i4 = (size_t)blockIdx.x * blockDim.x + threadIdx.x;
    if (i4 * 4 >= (size_t)VV * DD) return;
    float4 v = *(const float4*)(Wo + i4 * 4);
    __half2* dst = (__half2*)(g_wo_h + i4 * 4);
    dst[0] = __floats2half2_rn(v.x, v.y);
    dst[1] = __floats2half2_rn(v.z, v.w);
}

// =====================================================================
// K1: xproj = emb[tok] @ Wx^T + bx   (M=4096, N=512, K=512)
// =====================================================================
__global__ void k1_xproj(const int* __restrict__ tok, const float* __restrict__ emb,
                         const float* __restrict__ Wx, const float* __restrict__ bx)
{
    __shared__ float As[16][64];
    __shared__ float Bs[16][64];
    __shared__ int toks[64];
    const int m0 = blockIdx.y * 64;
    const int n0 = blockIdx.x * 64;
    const int tid = threadIdx.x;
    if (tid < 64) toks[tid] = tok[m0 + tid];
    __syncthreads();
    const int tm = tid >> 4, tn = tid & 15;
    const int lr = tid >> 2;
    const int lk = (tid & 3) << 2;
    const float* arow = emb + (size_t)toks[lr] * DD + lk;
    const float* brow = Wx + (size_t)(n0 + lr) * DD + lk;
    float acc[4][4] = {};
    for (int k0 = 0; k0 < DD; k0 += 16) {
        float4 av = *(const float4*)(arow + k0);
        float4 bv = *(const float4*)(brow + k0);
        __syncthreads();
        As[lk + 0][lr] = av.x; As[lk + 1][lr] = av.y;
        As[lk + 2][lr] = av.z; As[lk + 3][lr] = av.w;
        Bs[lk + 0][lr] = bv.x; Bs[lk + 1][lr] = bv.y;
        Bs[lk + 2][lr] = bv.z; Bs[lk + 3][lr] = bv.w;
        __syncthreads();
        #pragma unroll
        for (int k = 0; k < 16; k++) {
            float a[4], b[4];
            *(float4*)a = *(const float4*)&As[k][tm * 4];
            *(float4*)b = *(const float4*)&Bs[k][tn * 4];
            #pragma unroll
            for (int i = 0; i < 4; i++)
                #pragma unroll
                for (int j = 0; j < 4; j++)
                    acc[i][j] = fmaf(a[i], b[j], acc[i][j]);
        }
    }
    #pragma unroll
    for (int i = 0; i < 4; i++) {
        const int m = m0 + tm * 4 + i;
        #pragma unroll
        for (int j = 0; j < 4; j++) {
            const int e = n0 + tn * 4 + j;
            g_xproj[(size_t)m * DD + e] = acc[i][j] + bx[e];
        }
    }
}

// =====================================================================
// K2: recurrence, 8-CTA cluster per batch (4 clusters), split cluster
// barrier + xproj prefetch (measured-best structure, 2024us total).
// f32x2 packed dots, LDS.128 h loads (d = 4*lane + 128*q).
// NEW: DSMEM broadcast spread to 1 store per lane (lane r stores value
// r>>3 to rank r&7) — drain depth at CL_ARRIVE drops 4 -> 1.
// =====================================================================
__global__ __launch_bounds__(512, 1) __cluster_dims__(8, 1, 1)
void k2_recur(const float* __restrict__ Wh, const float* __restrict__ bh)
{
    __shared__ float sh[2][DD];
    const int tid = threadIdx.x;
    const int lane = tid & 31;
    const int w = tid >> 5;                 // 0..15
    const int batch = blockIdx.x >> 3;
    const int crank = blockIdx.x & 7;
    const int e_base = crank * 64 + w * 4;  // this warp's 4 e's

    // packed weights: wp[e][2q+p] covers d = 4*lane + 128*q + 2p (+1)
    unsigned long long wp[4][8];
    float bias[4];
    #pragma unroll
    for (int j = 0; j < 4; j++) {
        bias[j] = bh[e_base + j];
        #pragma unroll
        for (int q = 0; q < 4; q++) {
            float4 wv = *(const float4*)(Wh + (size_t)(e_base + j) * DD + 4 * lane + 128 * q);
            wp[j][2 * q]     = pk2(wv.x, wv.y);
            wp[j][2 * q + 1] = pk2(wv.z, wv.w);
        }
    }
    const float* xp = g_xproj + (size_t)batch * LL * DD;

    const int bj = lane >> 3;       // value this lane broadcasts (0..3)
    const int brk = lane & 7;       // destination rank

    // t = 0: h_prev = 0
    {
        float v[4];
        #pragma unroll
        for (int j = 0; j < 4; j++)
            v[j] = fmaxf(bias[j] + __ldcg(xp + e_base + j), 0.f);
        st_cluster_f32(smem_u32(&sh[0][e_base + bj]), brk, v[bj]);
        if (lane == 8) {
            __half2* dst = (__half2*)(g_hs_h + (size_t)(batch * LL) * DD + e_base);
            dst[0] = __floats2half2_rn(v[0], v[1]);
            dst[1] = __floats2half2_rn(v[2], v[3]);
        }
    }
    CL_ARRIVE();

    // prefetch xv for t = 1
    float xv_n[4];
    #pragma unroll
    for (int j = 0; j < 4; j++)
        xv_n[j] = __ldcg(xp + (size_t)1 * DD + e_base + j);

    for (int t = 1; t < LL; t++) {
        CL_WAIT();                      // h_{t-1} stores now visible

        float xv[4];
        #pragma unroll
        for (int j = 0; j < 4; j++) xv[j] = xv_n[j];

        // prefetch next step's xproj FIRST (LDG leaves before LDS chain)
        if (t + 1 < LL) {
            #pragma unroll
            for (int j = 0; j < 4; j++)
                xv_n[j] = __ldcg(xp + (size_t)(t + 1) * DD + e_base + j);
        }

        // h: 4x LDS.128, pack to f32x2
        const float* hb = sh[(t - 1) & 1];
        unsigned long long hp[8];
        #pragma unroll
        for (int q = 0; q < 4; q++) {
            float4 hv = *(const float4*)(hb + 4 * lane + 128 * q);
            hp[2 * q]     = pk2(hv.x, hv.y);
            hp[2 * q + 1] = pk2(hv.z, hv.w);
        }

        // 4 dots via packed FMA (32 f32x2 ops)
        float acc[4];
        #pragma unroll
        for (int j = 0; j < 4; j++) {
            unsigned long long a2 = 0ull;
            #pragma unroll
            for (int q = 0; q < 8; q++)
                fma2(a2, wp[j][q], hp[q]);
            float2 h2 = upk2(a2);
            acc[j] = h2.x + h2.y;
        }

        #pragma unroll
        for (int off = 16; off > 0; off >>= 1)
            #pragma unroll
            for (int j = 0; j < 4; j++)
                acc[j] += __shfl_xor_sync(0xffffffffu, acc[j], off);

        float v[4];
        #pragma unroll
        for (int j = 0; j < 4; j++)
            v[j] = fmaxf(acc[j] + bias[j] + xv[j], 0.f);

        if (t < LL - 1) {
            // spread broadcast: ONE st.shared::cluster per lane
            st_cluster_f32(smem_u32(&sh[t & 1][e_base + bj]), brk, v[bj]);
            CL_ARRIVE();
        }
        if (lane == 8) {
            __half2* dst = (__half2*)(g_hs_h + (size_t)(batch * LL + t) * DD + e_base);
            dst[0] = __floats2half2_rn(v[0], v[1]);
            dst[1] = __floats2half2_rn(v[2], v[3]);
        }
    }
}

// =====================================================================
// K3: out = hs @ Wo^T + bo  (M=4096, N=50257, K=512) — fp16 HMMA.
// CTA 128x128, warp tile 64x32 (2m x 4n), BK=64, 3-stage cp.async,
// 2 CTAs/SM, single sync per chunk (no trailing sync: issue(c+2)
// targets stage (c-1)%3 whose reads finished before the top sync).
// bo tile in smem. VV odd => scalar fp32 stores. (measured 678-684us)
// =====================================================================
#define K3_BM 128
#define K3_BN 128
#define K3_BKH 64
#define K3_NCH (DD / K3_BKH)                     // 8
#define K3_STAGE_BYTES ((K3_BM + K3_BN) * 128)   // 32768
#define K3_STAGES 3
#define K3_SMEM_BYTES (K3_STAGES * K3_STAGE_BYTES + K3_BN * 4)  // 98816

__global__ __launch_bounds__(256, 2)
void k3_mma(const float* __restrict__ bo, float* __restrict__ out)
{
    extern __shared__ __align__(1024) char smc[];
    const uint32_t smem_base = smem_u32(smc);
    float* bo_s = (float*)(smc + K3_STAGES * K3_STAGE_BYTES);
    const int tid = threadIdx.x;
    const int wid = tid >> 5;
    const int lane = tid & 31;
    const int m0 = blockIdx.x * K3_BM;
    const int n0 = blockIdx.y * K3_BN;
    const int warp_m = (wid & 1) * 64;
    const int warp_n = (wid >> 1) * 32;

    if (tid < K3_BN) {
        const int v = n0 + tid;
        bo_s[tid] = (v < VV) ? bo[v] : 0.f;
    }

    // ---- loader: 16B segs, swizzled 128B rows
    const int seg = tid & 7;
    const int r0 = tid >> 3;      // 0..31
    auto issue = [&](int c, int s) {
        const uint32_t abase = smem_base + s * K3_STAGE_BYTES;
        const uint32_t bbase = abase + K3_BM * 128;
        const __half* asrc = g_hs_h + (size_t)(m0 + r0) * DD + c * K3_BKH + seg * 8;
        #pragma unroll
        for (int i = 0; i < 4; i++) {
            const int row = r0 + 32 * i;
            cpa16(abase + SWZ128(row * 128 + seg * 16), asrc + (size_t)32 * i * DD, true);
        }
        #pragma unroll
        for (int i = 0; i < 4; i++) {
            const int row = r0 + 32 * i;
            const int v = n0 + row;
            const __half* bsrc = g_wo_h + (size_t)(v < VV ? v : 0) * DD + c * K3_BKH + seg * 8;
            cpa16(bbase + SWZ128(row * 128 + seg * 16), bsrc, v < VV);
        }
        cpa_commit();
    };

    issue(0, 0);
    issue(1, 1);

    // ldmatrix lane geometry
    int arow[4], axor[4];
    #pragma unroll
    for (int f = 0; f < 4; f++) {
        const int row = warp_m + f * 16 + (lane & 15);
        arow[f] = row * 128;
        axor[f] = (row & 7) * 16;
    }
    const int acol0 = (lane >> 4) * 16;
    int brow[2], bxor[2];
    #pragma unroll
    for (int g = 0; g < 2; g++) {
        const int nr = warp_n + g * 16 + ((lane & 16) >> 1) + (lane & 7);
        brow[g] = nr * 128;
        bxor[g] = (nr & 7) * 16;
    }
    const int bcol0 = ((lane >> 3) & 1) * 16;

    float acc[4][4][4];
    #pragma unroll
    for (int i = 0; i < 4; i++)
        #pragma unroll
        for (int j = 0; j < 4; j++)
            #pragma unroll
            for (int q = 0; q < 4; q++) acc[i][j][q] = 0.f;

    for (int c = 0; c < K3_NCH; c++) {
        if (c == K3_NCH - 1) cpa_wait<0>(); else cpa_wait<1>();
        __syncthreads();
        if (c + 2 < K3_NCH) issue(c + 2, (c + 2) % K3_STAGES);

        const uint32_t Ast = smem_base + (c % K3_STAGES) * K3_STAGE_BYTES;
        const uint32_t Bst = Ast + K3_BM * 128;

        #pragma unroll
        for (int ks = 0; ks < 4; ks++) {
            uint32_t A[4][4];
            #pragma unroll
            for (int f = 0; f < 4; f++)
                ldm4(A[f], Ast + arow[f] + ((acol0 + 32 * ks) ^ axor[f]));
            uint32_t Bf[2][4];
            #pragma unroll
            for (int g = 0; g < 2; g++)
                ldm4(Bf[g], Bst + brow[g] + ((bcol0 + 32 * ks) ^ bxor[g]));
            #pragma unroll
            for (int fm = 0; fm < 4; fm++)
                #pragma unroll
                for (int g = 0; g < 2; g++) {
                    mma16816(acc[fm][2 * g],     A[fm], Bf[g][0], Bf[g][1]);
                    mma16816(acc[fm][2 * g + 1], A[fm], Bf[g][2], Bf[g][3]);
                }
        }
        // no trailing sync (see header comment)
    }

    // ---- epilogue: scalar 32-bit stores (VV odd => rows only 4B-aligned)
    #pragma unroll
    for (int fm = 0; fm < 4; fm++) {
        const int m = m0 + warp_m + fm * 16 + (lane >> 2);
        float* orow0 = out + (size_t)m * VV;
        float* orow1 = out + (size_t)(m + 8) * VV;
        #pragma unroll
        for (int fn = 0; fn < 4; fn++) {
            const int nloc = warp_n + fn * 8 + 2 * (lane & 3);
            const int v = n0 + nloc;
            if (v < VV) {
                const float b0 = bo_s[nloc];
                orow0[v] = acc[fm][fn][0] + b0;
                orow1[v] = acc[fm][fn][2] + b0;
            }
            if (v + 1 < VV) {
                const float b1 = bo_s[nloc + 1];
                orow0[v + 1] = acc[fm][fn][1] + b1;
                orow1[v + 1] = acc[fm][fn][3] + b1;
            }
        }
    }
}

// =====================================================================
extern "C" void kernel_launch(void* const* d_in, const int* in_sizes, int n_in,
                              void* d_out, int out_size)
{
    const int*   tok = (const int*)d_in[0];
    const float* emb = (const float*)d_in[1];
    const float* Wh  = (const float*)d_in[2];
    const float* bh  = (const float*)d_in[3];
    const float* Wx  = (const float*)d_in[4];
    const float* bx  = (const float*)d_in[5];
    const float* Wo  = (const float*)d_in[6];
    const float* bo  = (const float*)d_in[7];
    float* out = (float*)d_out;

    const size_t n4 = ((size_t)VV * DD) / 4;
    k0_conv<<<(unsigned)((n4 + 255) / 256), 256>>>(Wo);

    dim3 g1(DD / 64, (BB * LL) / 64);
    k1_xproj<<<g1, 256>>>(tok, emb, Wx, bx);

    k2_recur<<<32, 512>>>(Wh, bh);   // 4 clusters of 8 CTAs

    cudaFuncSetAttribute(k3_mma, cudaFuncAttributeMaxDynamicSharedMemorySize, K3_SMEM_BYTES);
    dim3 g3((BB * LL) / K3_BM, (VV + K3_BN - 1) / K3_BN);   // (32, 393), M fastest
    k3_mma<<<g3, 256, K3_SMEM_BYTES>>>(bo, out);
}

// round 14
// speedup vs baseline: 1.6932x; 1.1044x over previous
#include <cuda_runtime.h>
#include <cuda_fp16.h>
#include <cstdint>

#define BB 4
#define LL 1024
#define VV 50257
#define DD 512

// ---- scratch (no allocations allowed) ----
__device__ float  g_xproj[BB * LL * DD];          // [b*L+t][D] fp32
__device__ __half g_hs_h[BB * LL * DD];           // [b*L+t][D] fp16 (K3 A operand)
__device__ __half g_wo_h[(size_t)VV * DD];        // Wo as fp16
__device__ unsigned g_prog[BB * 8];               // per-(batch,chunk) completion (target 128)
__device__ unsigned g_ready;                      // K2 residency count (target 32)

// =====================================================================
// helpers (base sm_103 ISA only — no 'a'-suffix features)
// =====================================================================
__device__ __forceinline__ uint32_t smem_u32(const void* p)
{
    uint32_t a;
    asm("{ .reg .u64 t; cvta.to.shared.u64 t, %1; cvt.u32.u64 %0, t; }" : "=r"(a) : "l"(p));
    return a;
}
#define SWZ128(x) ((x) ^ (((x) >> 3) & 0x70))

__device__ __forceinline__ void cpa16(uint32_t dst, const void* src, bool valid)
{
    asm volatile("cp.async.cg.shared.global [%0], [%1], 16, %2;"
                 :: "r"(dst), "l"(src), "r"(valid ? 16 : 0));
}
__device__ __forceinline__ void cpa_commit() { asm volatile("cp.async.commit_group;"); }
template <int N> __device__ __forceinline__ void cpa_wait() { asm volatile("cp.async.wait_group %0;" :: "n"(N)); }

__device__ __forceinline__ void ldm4(uint32_t* r, uint32_t addr)
{
    asm volatile("ldmatrix.sync.aligned.m8n8.x4.shared.b16 {%0,%1,%2,%3}, [%4];"
                 : "=r"(r[0]), "=r"(r[1]), "=r"(r[2]), "=r"(r[3]) : "r"(addr));
}
__device__ __forceinline__ void mma16816(float* c, const uint32_t* a, uint32_t b0, uint32_t b1)
{
    asm volatile("mma.sync.aligned.m16n8k16.row.col.f32.f16.f16.f32 "
                 "{%0,%1,%2,%3}, {%4,%5,%6,%7}, {%8,%9}, {%0,%1,%2,%3};"
                 : "+f"(c[0]), "+f"(c[1]), "+f"(c[2]), "+f"(c[3])
                 : "r"(a[0]), "r"(a[1]), "r"(a[2]), "r"(a[3]), "r"(b0), "r"(b1));
}
__device__ __forceinline__ void st_cluster_f32(uint32_t laddr, uint32_t rank, float v)
{
    uint32_t ra;
    asm volatile("mapa.shared::cluster.u32 %0, %1, %2;" : "=r"(ra) : "r"(laddr), "r"(rank));
    asm volatile("st.shared::cluster.f32 [%0], %1;" :: "r"(ra), "f"(v) : "memory");
}
#define CL_ARRIVE() asm volatile("barrier.cluster.arrive.aligned;" ::: "memory")
#define CL_WAIT()   asm volatile("barrier.cluster.wait.aligned;" ::: "memory")

// packed f32x2 (base sm_103 ISA)
__device__ __forceinline__ unsigned long long pk2(float lo, float hi)
{
    unsigned long long r;
    asm("mov.b64 %0, {%1, %2};" : "=l"(r) : "f"(lo), "f"(hi));
    return r;
}
__device__ __forceinline__ void fma2(unsigned long long& d, unsigned long long a, unsigned long long b)
{
    asm("fma.rn.f32x2 %0, %1, %2, %0;" : "+l"(d) : "l"(a), "l"(b));
}
__device__ __forceinline__ float2 upk2(unsigned long long v)
{
    float2 r;
    asm("mov.b64 {%0, %1}, %2;" : "=f"(r.x), "=f"(r.y) : "l"(v));
    return r;
}

__device__ __forceinline__ void publish_chunk(unsigned* p)
{
    asm volatile("red.add.release.gpu.u32 [%0], %1;" :: "l"(p), "r"(1u) : "memory");
}
__device__ __forceinline__ void wait_count(const unsigned* p, unsigned target)
{
    unsigned v;
    while (true) {
        asm volatile("ld.acquire.gpu.u32 %0, [%1];" : "=r"(v) : "l"(p) : "memory");
        if (v >= target) break;
        __nanosleep(512);
    }
}

// =====================================================================
// K0: Wo fp32 -> fp16
// =====================================================================
__global__ void k0_conv(const float* __restrict__ Wo)
{
    const size_t i4 = (size_t)blockIdx.x * blockDim.x + threadIdx.x;
    if (i4 * 4 >= (size_t)VV * DD) return;
    float4 v = *(const float4*)(Wo + i4 * 4);
    __half2* dst = (__half2*)(g_wo_h + i4 * 4);
    dst[0] = __floats2half2_rn(v.x, v.y);
    dst[1] = __floats2half2_rn(v.z, v.w);
}

// =====================================================================
// K1: xproj = emb[tok] @ Wx^T + bx   (M=4096, N=512, K=512)
// Also resets the K2->K3 progress counters (every launch; replay-safe).
// =====================================================================
__global__ void k1_xproj(const int* __restrict__ tok, const float* __restrict__ emb,
                         const float* __restrict__ Wx, const float* __restrict__ bx)
{
    if (blockIdx.x == 0 && blockIdx.y == 0 && threadIdx.x < BB * 8 + 1) {
        if (threadIdx.x < BB * 8) g_prog[threadIdx.x] = 0;
        else g_ready = 0;
    }
    __shared__ float As[16][64];
    __shared__ float Bs[16][64];
    __shared__ int toks[64];
    const int m0 = blockIdx.y * 64;
    const int n0 = blockIdx.x * 64;
    const int tid = threadIdx.x;
    if (tid < 64) toks[tid] = tok[m0 + tid];
    __syncthreads();
    const int tm = tid >> 4, tn = tid & 15;
    const int lr = tid >> 2;
    const int lk = (tid & 3) << 2;
    const float* arow = emb + (size_t)toks[lr] * DD + lk;
    const float* brow = Wx + (size_t)(n0 + lr) * DD + lk;
    float acc[4][4] = {};
    for (int k0 = 0; k0 < DD; k0 += 16) {
        float4 av = *(const float4*)(arow + k0);
        float4 bv = *(const float4*)(brow + k0);
        __syncthreads();
        As[lk + 0][lr] = av.x; As[lk + 1][lr] = av.y;
        As[lk + 2][lr] = av.z; As[lk + 3][lr] = av.w;
        Bs[lk + 0][lr] = bv.x; Bs[lk + 1][lr] = bv.y;
        Bs[lk + 2][lr] = bv.z; Bs[lk + 3][lr] = bv.w;
        __syncthreads();
        #pragma unroll
        for (int k = 0; k < 16; k++) {
            float a[4], b[4];
            *(float4*)a = *(const float4*)&As[k][tm * 4];
            *(float4*)b = *(const float4*)&Bs[k][tn * 4];
            #pragma unroll
            for (int i = 0; i < 4; i++)
                #pragma unroll
                for (int j = 0; j < 4; j++)
                    acc[i][j] = fmaf(a[i], b[j], acc[i][j]);
        }
    }
    #pragma unroll
    for (int i = 0; i < 4; i++) {
        const int m = m0 + tm * 4 + i;
        #pragma unroll
        for (int j = 0; j < 4; j++) {
            const int e = n0 + tn * 4 + j;
            g_xproj[(size_t)m * DD + e] = acc[i][j] + bx[e];
        }
    }
}

// =====================================================================
// K2: recurrence (round-13 measured-best) + progress publication.
// 8-CTA cluster per batch (4 clusters), split cluster barrier, xproj
// prefetch, f32x2 dots, 1-store-per-lane DSMEM broadcast.
// Every 128 steps each lane-8 thread release-adds +1 to the chunk
// counter (128 arrivals => all hs stores for the chunk are visible).
// =====================================================================
__global__ __launch_bounds__(512, 1) __cluster_dims__(8, 1, 1)
void k2_recur(const float* __restrict__ Wh, const float* __restrict__ bh)
{
    __shared__ float sh[2][DD];
    const int tid = threadIdx.x;
    const int lane = tid & 31;
    const int w = tid >> 5;                 // 0..15
    const int batch = blockIdx.x >> 3;
    const int crank = blockIdx.x & 7;
    const int e_base = crank * 64 + w * 4;  // this warp's 4 e's

    if (tid == 0) atomicAdd(&g_ready, 1u);  // residency mark for the gate

    unsigned long long wp[4][8];
    float bias[4];
    #pragma unroll
    for (int j = 0; j < 4; j++) {
        bias[j] = bh[e_base + j];
        #pragma unroll
        for (int q = 0; q < 4; q++) {
            float4 wv = *(const float4*)(Wh + (size_t)(e_base + j) * DD + 4 * lane + 128 * q);
            wp[j][2 * q]     = pk2(wv.x, wv.y);
            wp[j][2 * q + 1] = pk2(wv.z, wv.w);
        }
    }
    const float* xp = g_xproj + (size_t)batch * LL * DD;

    const int bj = lane >> 3;       // value this lane broadcasts (0..3)
    const int brk = lane & 7;       // destination rank

    // t = 0: h_prev = 0
    {
        float v[4];
        #pragma unroll
        for (int j = 0; j < 4; j++)
            v[j] = fmaxf(bias[j] + __ldcg(xp + e_base + j), 0.f);
        st_cluster_f32(smem_u32(&sh[0][e_base + bj]), brk, v[bj]);
        if (lane == 8) {
            __half2* dst = (__half2*)(g_hs_h + (size_t)(batch * LL) * DD + e_base);
            dst[0] = __floats2half2_rn(v[0], v[1]);
            dst[1] = __floats2half2_rn(v[2], v[3]);
        }
    }
    CL_ARRIVE();

    float xv_n[4];
    #pragma unroll
    for (int j = 0; j < 4; j++)
        xv_n[j] = __ldcg(xp + (size_t)1 * DD + e_base + j);

    for (int t = 1; t < LL; t++) {
        CL_WAIT();

        float xv[4];
        #pragma unroll
        for (int j = 0; j < 4; j++) xv[j] = xv_n[j];

        if (t + 1 < LL) {
            #pragma unroll
            for (int j = 0; j < 4; j++)
                xv_n[j] = __ldcg(xp + (size_t)(t + 1) * DD + e_base + j);
        }

        const float* hb = sh[(t - 1) & 1];
        unsigned long long hp[8];
        #pragma unroll
        for (int q = 0; q < 4; q++) {
            float4 hv = *(const float4*)(hb + 4 * lane + 128 * q);
            hp[2 * q]     = pk2(hv.x, hv.y);
            hp[2 * q + 1] = pk2(hv.z, hv.w);
        }

        float acc[4];
        #pragma unroll
        for (int j = 0; j < 4; j++) {
            unsigned long long a2 = 0ull;
            #pragma unroll
            for (int q = 0; q < 8; q++)
                fma2(a2, wp[j][q], hp[q]);
            float2 h2 = upk2(a2);
            acc[j] = h2.x + h2.y;
        }

        #pragma unroll
        for (int off = 16; off > 0; off >>= 1)
            #pragma unroll
            for (int j = 0; j < 4; j++)
                acc[j] += __shfl_xor_sync(0xffffffffu, acc[j], off);

        float v[4];
        #pragma unroll
        for (int j = 0; j < 4; j++)
            v[j] = fmaxf(acc[j] + bias[j] + xv[j], 0.f);

        if (t < LL - 1) {
            st_cluster_f32(smem_u32(&sh[t & 1][e_base + bj]), brk, v[bj]);
            CL_ARRIVE();
        }
        if (lane == 8) {
            __half2* dst = (__half2*)(g_hs_h + (size_t)(batch * LL + t) * DD + e_base);
            dst[0] = __floats2half2_rn(v[0], v[1]);
            dst[1] = __floats2half2_rn(v[2], v[3]);
            if ((t & 127) == 127)
                publish_chunk(&g_prog[batch * 8 + (t >> 7)]);   // release: orders this thread's hs stores
        }
    }
}

// =====================================================================
// gate: hold the fork stream until all 32 K2 CTAs are resident, so K3
// chunk CTAs can never occupy the SMs K2's clusters need (deadlock-free:
// this single CTA leaves 147 SMs for K2).
// =====================================================================
__global__ void k_gate()
{
    if (threadIdx.x == 0) wait_count(&g_ready, 32u);
}

// =====================================================================
// K3 chunk: out tile for timestep range [chunk*128, chunk*128+128).
// Polls the (batch,chunk) counter (==128) before touching hs.
// Body identical to the measured 677us k3_mma. grid=(4 batches, 393 n).
// =====================================================================
#define K3_BM 128
#define K3_BN 128
#define K3_BKH 64
#define K3_NCH (DD / K3_BKH)                     // 8
#define K3_STAGE_BYTES ((K3_BM + K3_BN) * 128)   // 32768
#define K3_STAGES 3
#define K3_SMEM_BYTES (K3_STAGES * K3_STAGE_BYTES + K3_BN * 4)  // 98816

__global__ __launch_bounds__(256, 2)
void k3_chunk(const float* __restrict__ bo, float* __restrict__ out, int chunk)
{
    extern __shared__ __align__(1024) char smc[];
    const uint32_t smem_base = smem_u32(smc);
    float* bo_s = (float*)(smc + K3_STAGES * K3_STAGE_BYTES);
    const int tid = threadIdx.x;
    const int wid = tid >> 5;
    const int lane = tid & 31;
    const int b = blockIdx.x;                         // batch (fast dim: Wo reuse)
    const int m0 = (b * 8 + chunk) * K3_BM;
    const int n0 = blockIdx.y * K3_BN;
    const int warp_m = (wid & 1) * 64;
    const int warp_n = (wid >> 1) * 32;

    // wait for producer: all hs rows for this (batch, chunk) published
    if (tid == 0) wait_count(&g_prog[b * 8 + chunk], 128u);
    __syncthreads();

    if (tid < K3_BN) {
        const int v = n0 + tid;
        bo_s[tid] = (v < VV) ? bo[v] : 0.f;
    }

    const int seg = tid & 7;
    const int r0 = tid >> 3;
    auto issue = [&](int c, int s) {
        const uint32_t abase = smem_base + s * K3_STAGE_BYTES;
        const uint32_t bbase = abase + K3_BM * 128;
        const __half* asrc = g_hs_h + (size_t)(m0 + r0) * DD + c * K3_BKH + seg * 8;
        #pragma unroll
        for (int i = 0; i < 4; i++) {
            const int row = r0 + 32 * i;
            cpa16(abase + SWZ128(row * 128 + seg * 16), asrc + (size_t)32 * i * DD, true);
        }
        #pragma unroll
        for (int i = 0; i < 4; i++) {
            const int row = r0 + 32 * i;
            const int v = n0 + row;
            const __half* bsrc = g_wo_h + (size_t)(v < VV ? v : 0) * DD + c * K3_BKH + seg * 8;
            cpa16(bbase + SWZ128(row * 128 + seg * 16), bsrc, v < VV);
        }
        cpa_commit();
    };

    issue(0, 0);
    issue(1, 1);

    int arow[4], axor[4];
    #pragma unroll
    for (int f = 0; f < 4; f++) {
        const int row = warp_m + f * 16 + (lane & 15);
        arow[f] = row * 128;
        axor[f] = (row & 7) * 16;
    }
    const int acol0 = (lane >> 4) * 16;
    int brow[2], bxor[2];
    #pragma unroll
    for (int g = 0; g < 2; g++) {
        const int nr = warp_n + g * 16 + ((lane & 16) >> 1) + (lane & 7);
        brow[g] = nr * 128;
        bxor[g] = (nr & 7) * 16;
    }
    const int bcol0 = ((lane >> 3) & 1) * 16;

    float acc[4][4][4];
    #pragma unroll
    for (int i = 0; i < 4; i++)
        #pragma unroll
        for (int j = 0; j < 4; j++)
            #pragma unroll
            for (int q = 0; q < 4; q++) acc[i][j][q] = 0.f;

    for (int c = 0; c < K3_NCH; c++) {
        if (c == K3_NCH - 1) cpa_wait<0>(); else cpa_wait<1>();
        __syncthreads();
        if (c + 2 < K3_NCH) issue(c + 2, (c + 2) % K3_STAGES);

        const uint32_t Ast = smem_base + (c % K3_STAGES) * K3_STAGE_BYTES;
        const uint32_t Bst = Ast + K3_BM * 128;

        #pragma unroll
        for (int ks = 0; ks < 4; ks++) {
            uint32_t A[4][4];
            #pragma unroll
            for (int f = 0; f < 4; f++)
                ldm4(A[f], Ast + arow[f] + ((acol0 + 32 * ks) ^ axor[f]));
            uint32_t Bf[2][4];
            #pragma unroll
            for (int g = 0; g < 2; g++)
                ldm4(Bf[g], Bst + brow[g] + ((bcol0 + 32 * ks) ^ bxor[g]));
            #pragma unroll
            for (int fm = 0; fm < 4; fm++)
                #pragma unroll
                for (int g = 0; g < 2; g++) {
                    mma16816(acc[fm][2 * g],     A[fm], Bf[g][0], Bf[g][1]);
                    mma16816(acc[fm][2 * g + 1], A[fm], Bf[g][2], Bf[g][3]);
                }
        }
    }

    #pragma unroll
    for (int fm = 0; fm < 4; fm++) {
        const int m = m0 + warp_m + fm * 16 + (lane >> 2);
        float* orow0 = out + (size_t)m * VV;
        float* orow1 = out + (size_t)(m + 8) * VV;
        #pragma unroll
        for (int fn = 0; fn < 4; fn++) {
            const int nloc = warp_n + fn * 8 + 2 * (lane & 3);
            const int v = n0 + nloc;
            if (v < VV) {
                const float b0 = bo_s[nloc];
                orow0[v] = acc[fm][fn][0] + b0;
                orow1[v] = acc[fm][fn][2] + b0;
            }
            if (v + 1 < VV) {
                const float b1 = bo_s[nloc + 1];
                orow0[v + 1] = acc[fm][fn][1] + b1;
                orow1[v + 1] = acc[fm][fn][3] + b1;
            }
        }
    }
}

// =====================================================================
extern "C" void kernel_launch(void* const* d_in, const int* in_sizes, int n_in,
                              void* d_out, int out_size)
{
    const int*   tok = (const int*)d_in[0];
    const float* emb = (const float*)d_in[1];
    const float* Wh  = (const float*)d_in[2];
    const float* bh  = (const float*)d_in[3];
    const float* Wx  = (const float*)d_in[4];
    const float* bx  = (const float*)d_in[5];
    const float* Wo  = (const float*)d_in[6];
    const float* bo  = (const float*)d_in[7];
    float* out = (float*)d_out;

    static cudaStream_t sB = nullptr;
    static cudaEvent_t evPre = nullptr, evJ = nullptr;
    if (sB == nullptr) {
        cudaStreamCreateWithFlags(&sB, cudaStreamNonBlocking);
        cudaEventCreateWithFlags(&evPre, cudaEventDisableTiming);
        cudaEventCreateWithFlags(&evJ, cudaEventDisableTiming);
    }
    cudaFuncSetAttribute(k3_chunk, cudaFuncAttributeMaxDynamicSharedMemorySize, K3_SMEM_BYTES);

    // ---- stream 0: K0, K1, then K2 (producer) ----
    const size_t n4 = ((size_t)VV * DD) / 4;
    k0_conv<<<(unsigned)((n4 + 255) / 256), 256>>>(Wo);

    dim3 g1(DD / 64, (BB * LL) / 64);
    k1_xproj<<<g1, 256>>>(tok, emb, Wx, bx);   // also resets g_prog / g_ready

    cudaEventRecord(evPre, (cudaStream_t)0);
    cudaStreamWaitEvent(sB, evPre, 0);

    k2_recur<<<32, 512>>>(Wh, bh);             // 4 clusters of 8 CTAs, publishes chunks

    // ---- stream B (consumer): gate, then 8 chunked K3 launches ----
    k_gate<<<1, 32, 0, sB>>>();
    for (int c = 0; c < 8; c++) {
        k3_chunk<<<dim3(BB, (VV + K3_BN - 1) / K3_BN), 256, K3_SMEM_BYTES, sB>>>(bo, out, c);
    }
    cudaEventRecord(evJ, sB);
    cudaStreamWaitEvent((cudaStream_t)0, evJ, 0);   // join: harness continues on stream 0
}

// round 15
// speedup vs baseline: 1.7274x; 1.0202x over previous
#include <cuda_runtime.h>
#include <cuda_fp16.h>
#include <cstdint>

#define BB 4
#define LL 1024
#define VV 50257
#define DD 512

// ---- scratch (no allocations allowed) ----
__device__ float  g_xproj[BB * LL * DD];          // [b*L+t][D] fp32
__device__ __half g_hs_h[BB * LL * DD];           // [b*L+t][D] fp16 (K3 A operand)
__device__ __half g_wo_h[(size_t)VV * DD];        // Wo as fp16
__device__ unsigned g_prog[BB * 8];               // per-(batch,chunk) completion (target 128)
__device__ unsigned g_ready;                      // K2 residency count (target 32)

// =====================================================================
// helpers (base sm_103 ISA only — no 'a'-suffix features)
// =====================================================================
__device__ __forceinline__ uint32_t smem_u32(const void* p)
{
    uint32_t a;
    asm("{ .reg .u64 t; cvta.to.shared.u64 t, %1; cvt.u32.u64 %0, t; }" : "=r"(a) : "l"(p));
    return a;
}
#define SWZ128(x) ((x) ^ (((x) >> 3) & 0x70))

__device__ __forceinline__ void cpa16(uint32_t dst, const void* src, bool valid)
{
    asm volatile("cp.async.cg.shared.global [%0], [%1], 16, %2;"
                 :: "r"(dst), "l"(src), "r"(valid ? 16 : 0));
}
__device__ __forceinline__ void cpa_commit() { asm volatile("cp.async.commit_group;"); }
template <int N> __device__ __forceinline__ void cpa_wait() { asm volatile("cp.async.wait_group %0;" :: "n"(N)); }

__device__ __forceinline__ void ldm4(uint32_t* r, uint32_t addr)
{
    asm volatile("ldmatrix.sync.aligned.m8n8.x4.shared.b16 {%0,%1,%2,%3}, [%4];"
                 : "=r"(r[0]), "=r"(r[1]), "=r"(r[2]), "=r"(r[3]) : "r"(addr));
}
__device__ __forceinline__ void mma16816(float* c, const uint32_t* a, uint32_t b0, uint32_t b1)
{
    asm volatile("mma.sync.aligned.m16n8k16.row.col.f32.f16.f16.f32 "
                 "{%0,%1,%2,%3}, {%4,%5,%6,%7}, {%8,%9}, {%0,%1,%2,%3};"
                 : "+f"(c[0]), "+f"(c[1]), "+f"(c[2]), "+f"(c[3])
                 : "r"(a[0]), "r"(a[1]), "r"(a[2]), "r"(a[3]), "r"(b0), "r"(b1));
}
__device__ __forceinline__ void st_cluster_f32(uint32_t laddr, uint32_t rank, float v)
{
    uint32_t ra;
    asm volatile("mapa.shared::cluster.u32 %0, %1, %2;" : "=r"(ra) : "r"(laddr), "r"(rank));
    asm volatile("st.shared::cluster.f32 [%0], %1;" :: "r"(ra), "f"(v) : "memory");
}
#define CL_ARRIVE() asm volatile("barrier.cluster.arrive.aligned;" ::: "memory")
#define CL_WAIT()   asm volatile("barrier.cluster.wait.aligned;" ::: "memory")

// packed f32x2 (base sm_103 ISA)
__device__ __forceinline__ unsigned long long pk2(float lo, float hi)
{
    unsigned long long r;
    asm("mov.b64 %0, {%1, %2};" : "=l"(r) : "f"(lo), "f"(hi));
    return r;
}
__device__ __forceinline__ void fma2(unsigned long long& d, unsigned long long a, unsigned long long b)
{
    asm("fma.rn.f32x2 %0, %1, %2, %0;" : "+l"(d) : "l"(a), "l"(b));
}
__device__ __forceinline__ float2 upk2(unsigned long long v)
{
    float2 r;
    asm("mov.b64 {%0, %1}, %2;" : "=f"(r.x), "=f"(r.y) : "l"(v));
    return r;
}

__device__ __forceinline__ void publish_chunk(unsigned* p)
{
    asm volatile("red.add.release.gpu.u32 [%0], %1;" :: "l"(p), "r"(1u) : "memory");
}
__device__ __forceinline__ void wait_count(const unsigned* p, unsigned target)
{
    unsigned v;
    while (true) {
        asm volatile("ld.acquire.gpu.u32 %0, [%1];" : "=r"(v) : "l"(p) : "memory");
        if (v >= target) break;
        __nanosleep(512);
    }
}

// =====================================================================
// K0: Wo fp32 -> fp16 (runs on stream B, overlapped with K1)
// =====================================================================
__global__ void k0_conv(const float* __restrict__ Wo)
{
    const size_t i4 = (size_t)blockIdx.x * blockDim.x + threadIdx.x;
    if (i4 * 4 >= (size_t)VV * DD) return;
    float4 v = *(const float4*)(Wo + i4 * 4);
    __half2* dst = (__half2*)(g_wo_h + i4 * 4);
    dst[0] = __floats2half2_rn(v.x, v.y);
    dst[1] = __floats2half2_rn(v.z, v.w);
}

// =====================================================================
// K1: xproj = emb[tok] @ Wx^T + bx   (M=4096, N=512, K=512)
// Also resets the K2->K3 progress counters (every launch; replay-safe).
// =====================================================================
__global__ void k1_xproj(const int* __restrict__ tok, const float* __restrict__ emb,
                         const float* __restrict__ Wx, const float* __restrict__ bx)
{
    if (blockIdx.x == 0 && blockIdx.y == 0 && threadIdx.x < BB * 8 + 1) {
        if (threadIdx.x < BB * 8) g_prog[threadIdx.x] = 0;
        else g_ready = 0;
    }
    __shared__ float As[16][64];
    __shared__ float Bs[16][64];
    __shared__ int toks[64];
    const int m0 = blockIdx.y * 64;
    const int n0 = blockIdx.x * 64;
    const int tid = threadIdx.x;
    if (tid < 64) toks[tid] = tok[m0 + tid];
    __syncthreads();
    const int tm = tid >> 4, tn = tid & 15;
    const int lr = tid >> 2;
    const int lk = (tid & 3) << 2;
    const float* arow = emb + (size_t)toks[lr] * DD + lk;
    const float* brow = Wx + (size_t)(n0 + lr) * DD + lk;
    float acc[4][4] = {};
    for (int k0 = 0; k0 < DD; k0 += 16) {
        float4 av = *(const float4*)(arow + k0);
        float4 bv = *(const float4*)(brow + k0);
        __syncthreads();
        As[lk + 0][lr] = av.x; As[lk + 1][lr] = av.y;
        As[lk + 2][lr] = av.z; As[lk + 3][lr] = av.w;
        Bs[lk + 0][lr] = bv.x; Bs[lk + 1][lr] = bv.y;
        Bs[lk + 2][lr] = bv.z; Bs[lk + 3][lr] = bv.w;
        __syncthreads();
        #pragma unroll
        for (int k = 0; k < 16; k++) {
            float a[4], b[4];
            *(float4*)a = *(const float4*)&As[k][tm * 4];
            *(float4*)b = *(const float4*)&Bs[k][tn * 4];
            #pragma unroll
            for (int i = 0; i < 4; i++)
                #pragma unroll
                for (int j = 0; j < 4; j++)
                    acc[i][j] = fmaf(a[i], b[j], acc[i][j]);
        }
    }
    #pragma unroll
    for (int i = 0; i < 4; i++) {
        const int m = m0 + tm * 4 + i;
        #pragma unroll
        for (int j = 0; j < 4; j++) {
            const int e = n0 + tn * 4 + j;
            g_xproj[(size_t)m * DD + e] = acc[i][j] + bx[e];
        }
    }
}

// =====================================================================
// K2: recurrence (round-13 measured-best) + progress publication.
// =====================================================================
__global__ __launch_bounds__(512, 1) __cluster_dims__(8, 1, 1)
void k2_recur(const float* __restrict__ Wh, const float* __restrict__ bh)
{
    __shared__ float sh[2][DD];
    const int tid = threadIdx.x;
    const int lane = tid & 31;
    const int w = tid >> 5;                 // 0..15
    const int batch = blockIdx.x >> 3;
    const int crank = blockIdx.x & 7;
    const int e_base = crank * 64 + w * 4;  // this warp's 4 e's

    if (tid == 0) atomicAdd(&g_ready, 1u);  // residency mark for the gate

    unsigned long long wp[4][8];
    float bias[4];
    #pragma unroll
    for (int j = 0; j < 4; j++) {
        bias[j] = bh[e_base + j];
        #pragma unroll
        for (int q = 0; q < 4; q++) {
            float4 wv = *(const float4*)(Wh + (size_t)(e_base + j) * DD + 4 * lane + 128 * q);
            wp[j][2 * q]     = pk2(wv.x, wv.y);
            wp[j][2 * q + 1] = pk2(wv.z, wv.w);
        }
    }
    const float* xp = g_xproj + (size_t)batch * LL * DD;

    const int bj = lane >> 3;       // value this lane broadcasts (0..3)
    const int brk = lane & 7;       // destination rank

    // t = 0: h_prev = 0
    {
        float v[4];
        #pragma unroll
        for (int j = 0; j < 4; j++)
            v[j] = fmaxf(bias[j] + __ldcg(xp + e_base + j), 0.f);
        st_cluster_f32(smem_u32(&sh[0][e_base + bj]), brk, v[bj]);
        if (lane == 8) {
            __half2* dst = (__half2*)(g_hs_h + (size_t)(batch * LL) * DD + e_base);
            dst[0] = __floats2half2_rn(v[0], v[1]);
            dst[1] = __floats2half2_rn(v[2], v[3]);
        }
    }
    CL_ARRIVE();

    float xv_n[4];
    #pragma unroll
    for (int j = 0; j < 4; j++)
        xv_n[j] = __ldcg(xp + (size_t)1 * DD + e_base + j);

    for (int t = 1; t < LL; t++) {
        CL_WAIT();

        float xv[4];
        #pragma unroll
        for (int j = 0; j < 4; j++) xv[j] = xv_n[j];

        if (t + 1 < LL) {
            #pragma unroll
            for (int j = 0; j < 4; j++)
                xv_n[j] = __ldcg(xp + (size_t)(t + 1) * DD + e_base + j);
        }

        const float* hb = sh[(t - 1) & 1];
        unsigned long long hp[8];
        #pragma unroll
        for (int q = 0; q < 4; q++) {
            float4 hv = *(const float4*)(hb + 4 * lane + 128 * q);
            hp[2 * q]     = pk2(hv.x, hv.y);
            hp[2 * q + 1] = pk2(hv.z, hv.w);
        }

        float acc[4];
        #pragma unroll
        for (int j = 0; j < 4; j++) {
            unsigned long long a2 = 0ull;
            #pragma unroll
            for (int q = 0; q < 8; q++)
                fma2(a2, wp[j][q], hp[q]);
            float2 h2 = upk2(a2);
            acc[j] = h2.x + h2.y;
        }

        #pragma unroll
        for (int off = 16; off > 0; off >>= 1)
            #pragma unroll
            for (int j = 0; j < 4; j++)
                acc[j] += __shfl_xor_sync(0xffffffffu, acc[j], off);

        float v[4];
        #pragma unroll
        for (int j = 0; j < 4; j++)
            v[j] = fmaxf(acc[j] + bias[j] + xv[j], 0.f);

        if (t < LL - 1) {
            st_cluster_f32(smem_u32(&sh[t & 1][e_base + bj]), brk, v[bj]);
            CL_ARRIVE();
        }
        if (lane == 8) {
            __half2* dst = (__half2*)(g_hs_h + (size_t)(batch * LL + t) * DD + e_base);
            dst[0] = __floats2half2_rn(v[0], v[1]);
            dst[1] = __floats2half2_rn(v[2], v[3]);
            if ((t & 127) == 127)
                publish_chunk(&g_prog[batch * 8 + (t >> 7)]);   // release: orders this thread's hs stores
        }
    }
}

// =====================================================================
// gate: hold stream B until all 32 K2 CTAs are resident (deadlock-free).
// =====================================================================
__global__ void k_gate()
{
    if (threadIdx.x == 0) wait_count(&g_ready, 32u);
}

// =====================================================================
// K3: ONE launch, chunk = blockIdx.z (slowest dim => CTAs scheduled in
// chunk-ascending order). Each CTA spins on its own (batch,chunk)
// counter, then runs the measured 677us-class body on its slice.
// grid = (4 batches, 393 ntiles, 8 chunks).
// =====================================================================
#define K3_BM 128
#define K3_BN 128
#define K3_BKH 64
#define K3_NCH (DD / K3_BKH)                     // 8
#define K3_STAGE_BYTES ((K3_BM + K3_BN) * 128)   // 32768
#define K3_STAGES 3
#define K3_SMEM_BYTES (K3_STAGES * K3_STAGE_BYTES + K3_BN * 4)  // 98816

__global__ __launch_bounds__(256, 2)
void k3_all(const float* __restrict__ bo, float* __restrict__ out)
{
    extern __shared__ __align__(1024) char smc[];
    const uint32_t smem_base = smem_u32(smc);
    float* bo_s = (float*)(smc + K3_STAGES * K3_STAGE_BYTES);
    const int tid = threadIdx.x;
    const int wid = tid >> 5;
    const int lane = tid & 31;
    const int b = blockIdx.x;                         // batch (fastest: Wo reuse)
    const int chunk = blockIdx.z;                     // slowest: scheduled in order
    const int m0 = (b * 8 + chunk) * K3_BM;
    const int n0 = blockIdx.y * K3_BN;
    const int warp_m = (wid & 1) * 64;
    const int warp_n = (wid >> 1) * 32;

    // wait for producer: all hs rows for this (batch, chunk) published
    if (tid == 0) wait_count(&g_prog[b * 8 + chunk], 128u);
    __syncthreads();

    if (tid < K3_BN) {
        const int v = n0 + tid;
        bo_s[tid] = (v < VV) ? bo[v] : 0.f;
    }

    const int seg = tid & 7;
    const int r0 = tid >> 3;
    auto issue = [&](int c, int s) {
        const uint32_t abase = smem_base + s * K3_STAGE_BYTES;
        const uint32_t bbase = abase + K3_BM * 128;
        const __half* asrc = g_hs_h + (size_t)(m0 + r0) * DD + c * K3_BKH + seg * 8;
        #pragma unroll
        for (int i = 0; i < 4; i++) {
            const int row = r0 + 32 * i;
            cpa16(abase + SWZ128(row * 128 + seg * 16), asrc + (size_t)32 * i * DD, true);
        }
        #pragma unroll
        for (int i = 0; i < 4; i++) {
            const int row = r0 + 32 * i;
            const int v = n0 + row;
            const __half* bsrc = g_wo_h + (size_t)(v < VV ? v : 0) * DD + c * K3_BKH + seg * 8;
            cpa16(bbase + SWZ128(row * 128 + seg * 16), bsrc, v < VV);
        }
        cpa_commit();
    };

    issue(0, 0);
    issue(1, 1);

    int arow[4], axor[4];
    #pragma unroll
    for (int f = 0; f < 4; f++) {
        const int row = warp_m + f * 16 + (lane & 15);
        arow[f] = row * 128;
        axor[f] = (row & 7) * 16;
    }
    const int acol0 = (lane >> 4) * 16;
    int brow[2], bxor[2];
    #pragma unroll
    for (int g = 0; g < 2; g++) {
        const int nr = warp_n + g * 16 + ((lane & 16) >> 1) + (lane & 7);
        brow[g] = nr * 128;
        bxor[g] = (nr & 7) * 16;
    }
    const int bcol0 = ((lane >> 3) & 1) * 16;

    float acc[4][4][4];
    #pragma unroll
    for (int i = 0; i < 4; i++)
        #pragma unroll
        for (int j = 0; j < 4; j++)
            #pragma unroll
            for (int q = 0; q < 4; q++) acc[i][j][q] = 0.f;

    for (int c = 0; c < K3_NCH; c++) {
        if (c == K3_NCH - 1) cpa_wait<0>(); else cpa_wait<1>();
        __syncthreads();
        if (c + 2 < K3_NCH) issue(c + 2, (c + 2) % K3_STAGES);

        const uint32_t Ast = smem_base + (c % K3_STAGES) * K3_STAGE_BYTES;
        const uint32_t Bst = Ast + K3_BM * 128;

        #pragma unroll
        for (int ks = 0; ks < 4; ks++) {
            uint32_t A[4][4];
            #pragma unroll
            for (int f = 0; f < 4; f++)
                ldm4(A[f], Ast + arow[f] + ((acol0 + 32 * ks) ^ axor[f]));
            uint32_t Bf[2][4];
            #pragma unroll
            for (int g = 0; g < 2; g++)
                ldm4(Bf[g], Bst + brow[g] + ((bcol0 + 32 * ks) ^ bxor[g]));
            #pragma unroll
            for (int fm = 0; fm < 4; fm++)
                #pragma unroll
                for (int g = 0; g < 2; g++) {
                    mma16816(acc[fm][2 * g],     A[fm], Bf[g][0], Bf[g][1]);
                    mma16816(acc[fm][2 * g + 1], A[fm], Bf[g][2], Bf[g][3]);
                }
        }
    }

    #pragma unroll
    for (int fm = 0; fm < 4; fm++) {
        const int m = m0 + warp_m + fm * 16 + (lane >> 2);
        float* orow0 = out + (size_t)m * VV;
        float* orow1 = out + (size_t)(m + 8) * VV;
        #pragma unroll
        for (int fn = 0; fn < 4; fn++) {
            const int nloc = warp_n + fn * 8 + 2 * (lane & 3);
            const int v = n0 + nloc;
            if (v < VV) {
                const float b0 = bo_s[nloc];
                orow0[v] = acc[fm][fn][0] + b0;
                orow1[v] = acc[fm][fn][2] + b0;
            }
            if (v + 1 < VV) {
                const float b1 = bo_s[nloc + 1];
                orow0[v + 1] = acc[fm][fn][1] + b1;
                orow1[v + 1] = acc[fm][fn][3] + b1;
            }
        }
    }
}

// =====================================================================
extern "C" void kernel_launch(void* const* d_in, const int* in_sizes, int n_in,
                              void* d_out, int out_size)
{
    const int*   tok = (const int*)d_in[0];
    const float* emb = (const float*)d_in[1];
    const float* Wh  = (const float*)d_in[2];
    const float* bh  = (const float*)d_in[3];
    const float* Wx  = (const float*)d_in[4];
    const float* bx  = (const float*)d_in[5];
    const float* Wo  = (const float*)d_in[6];
    const float* bo  = (const float*)d_in[7];
    float* out = (float*)d_out;

    static cudaStream_t sB = nullptr;
    static cudaEvent_t evPre = nullptr, evJ = nullptr;
    if (sB == nullptr) {
        cudaStreamCreateWithFlags(&sB, cudaStreamNonBlocking);
        cudaEventCreateWithFlags(&evPre, cudaEventDisableTiming);
        cudaEventCreateWithFlags(&evJ, cudaEventDisableTiming);
    }
    cudaFuncSetAttribute(k3_all, cudaFuncAttributeMaxDynamicSharedMemorySize, K3_SMEM_BYTES);

    // ---- stream 0: K1 (resets counters), then K2 (producer) ----
    dim3 g1(DD / 64, (BB * LL) / 64);
    k1_xproj<<<g1, 256>>>(tok, emb, Wx, bx);

    cudaEventRecord(evPre, (cudaStream_t)0);
    cudaStreamWaitEvent(sB, evPre, 0);

    k2_recur<<<32, 512>>>(Wh, bh);             // 4 clusters of 8 CTAs, publishes chunks

    // ---- stream B (consumer): K0 (overlaps K2 start), gate, single K3 ----
    const size_t n4 = ((size_t)VV * DD) / 4;
    k0_conv<<<(unsigned)((n4 + 255) / 256), 256, 0, sB>>>(Wo);
    k_gate<<<1, 32, 0, sB>>>();
    k3_all<<<dim3(BB, (VV + K3_BN - 1) / K3_BN, 8), 256, K3_SMEM_BYTES, sB>>>(bo, out);

    cudaEventRecord(evJ, sB);
    cudaStreamWaitEvent((cudaStream_t)0, evJ, 0);   // join: harness continues on stream 0
}